// round 7
// baseline (speedup 1.0000x reference)
#include <cuda_runtime.h>
#include <cuda_bf16.h>
#include <stdint.h>

#define B_  8
#define T_  2048
#define E_  1024
#define H_  128
#define BT_ (B_*T_)

// ---- global scratch ----
__device__ __nv_bfloat16 gx_h[BT_*E_];
__device__ __nv_bfloat16 gx_l[BT_*E_];
__device__ __nv_bfloat16 gw_h[3][E_*H_];
__device__ __nv_bfloat16 gw_l[3][E_*H_];
__device__ __nv_bfloat16 gq_h[BT_*H_];
__device__ __nv_bfloat16 gq_l[BT_*H_];
__device__ __nv_bfloat16 gk_h[BT_*H_];
__device__ __nv_bfloat16 gk_l[BT_*H_];
__device__ __nv_bfloat16 gv_h[BT_*H_];
__device__ __nv_bfloat16 gv_l[BT_*H_];

// ---- helpers ----
__device__ __forceinline__ void ldm_x4(uint32_t* r, const void* p) {
    uint32_t a = (uint32_t)__cvta_generic_to_shared(p);
    asm volatile("ldmatrix.sync.aligned.m8n8.x4.shared.b16 {%0,%1,%2,%3}, [%4];"
                 : "=r"(r[0]), "=r"(r[1]), "=r"(r[2]), "=r"(r[3]) : "r"(a));
}
__device__ __forceinline__ void ldm_x4_t(uint32_t* r, const void* p) {
    uint32_t a = (uint32_t)__cvta_generic_to_shared(p);
    asm volatile("ldmatrix.sync.aligned.m8n8.x4.trans.shared.b16 {%0,%1,%2,%3}, [%4];"
                 : "=r"(r[0]), "=r"(r[1]), "=r"(r[2]), "=r"(r[3]) : "r"(a));
}
__device__ __forceinline__ void mma16816(float* d, const uint32_t* a, const uint32_t* b) {
    asm volatile("mma.sync.aligned.m16n8k16.row.col.f32.bf16.bf16.f32 "
                 "{%0,%1,%2,%3}, {%4,%5,%6,%7}, {%8,%9}, {%0,%1,%2,%3};"
                 : "+f"(d[0]), "+f"(d[1]), "+f"(d[2]), "+f"(d[3])
                 : "r"(a[0]), "r"(a[1]), "r"(a[2]), "r"(a[3]), "r"(b[0]), "r"(b[1]));
}
__device__ __forceinline__ uint32_t pack_hi2(float a, float b) {
    __nv_bfloat162 h;
    h.x = __float2bfloat16_rn(a);
    h.y = __float2bfloat16_rn(b);
    return *reinterpret_cast<uint32_t*>(&h);
}
__device__ __forceinline__ uint32_t pack_lo2(float a, float b) {
    __nv_bfloat16 ha = __float2bfloat16_rn(a);
    __nv_bfloat16 hb = __float2bfloat16_rn(b);
    __nv_bfloat162 l;
    l.x = __float2bfloat16_rn(a - __bfloat162float(ha));
    l.y = __float2bfloat16_rn(b - __bfloat162float(hb));
    return *reinterpret_cast<uint32_t*>(&l);
}
__device__ __forceinline__ void cp16(void* smem, const void* gmem) {
    uint32_t a = (uint32_t)__cvta_generic_to_shared(smem);
    asm volatile("cp.async.cg.shared.global [%0], [%1], 16;" :: "r"(a), "l"(gmem));
}
__device__ __forceinline__ void cp_commit() { asm volatile("cp.async.commit_group;"); }
template<int N> __device__ __forceinline__ void cp_wait() {
    asm volatile("cp.async.wait_group %0;" :: "n"(N));
}

// ---------------------------------------------------------------------------
// Split kernels
// ---------------------------------------------------------------------------
__global__ void split_x_kernel(const float* __restrict__ x)
{
    int i = blockIdx.x * 256 + threadIdx.x;
    float4 v = reinterpret_cast<const float4*>(x)[i];
    uint2 hv, lv;
    hv.x = pack_hi2(v.x, v.y); hv.y = pack_hi2(v.z, v.w);
    lv.x = pack_lo2(v.x, v.y); lv.y = pack_lo2(v.z, v.w);
    reinterpret_cast<uint2*>(gx_h)[i] = hv;
    reinterpret_cast<uint2*>(gx_l)[i] = lv;
}

__global__ void split_w_kernel(const float* __restrict__ Wq,
                               const float* __restrict__ Wk,
                               const float* __restrict__ Wv)
{
    const float* W = (blockIdx.y == 0) ? Wq : (blockIdx.y == 1) ? Wk : Wv;
    __nv_bfloat16* oh = gw_h[blockIdx.y];
    __nv_bfloat16* ol = gw_l[blockIdx.y];
    int i = blockIdx.x * 256 + threadIdx.x;
    float4 v = reinterpret_cast<const float4*>(W)[i];
    uint2 hv, lv;
    hv.x = pack_hi2(v.x, v.y); hv.y = pack_hi2(v.z, v.w);
    lv.x = pack_lo2(v.x, v.y); lv.y = pack_lo2(v.z, v.w);
    reinterpret_cast<uint2*>(oh)[i] = hv;
    reinterpret_cast<uint2*>(ol)[i] = lv;
}

// ---------------------------------------------------------------------------
// Projection: 64x128 tile, BK=64, 4 warps, 2-stage cp.async, 2 CTAs/SM.
// ---------------------------------------------------------------------------
#define PX_ (64*72)
#define PW_ (64*136)

__global__ __launch_bounds__(128, 2) void proj_mma()
{
    extern __shared__ __nv_bfloat16 smp[];
    __nv_bfloat16* Xh = smp;               // [2][64*72]
    __nv_bfloat16* Xl = Xh + 2*PX_;
    __nv_bfloat16* Wh = Xl + 2*PX_;        // [2][64*136]
    __nv_bfloat16* Wl = Wh + 2*PW_;

    const int mat = blockIdx.y;
    const __nv_bfloat16* wh = gw_h[mat];
    const __nv_bfloat16* wl = gw_l[mat];
    __nv_bfloat16 *oh, *ol;
    if (mat == 0)      { oh = gq_h; ol = gq_l; }
    else if (mat == 1) { oh = gk_h; ol = gk_l; }
    else               { oh = gv_h; ol = gv_l; }

    const int r0   = blockIdx.x * 64;
    const int tid  = threadIdx.x;
    const int wrp  = tid >> 5;
    const int lane = tid & 31;
    const int g    = lane >> 2;
    const int tg   = lane & 3;

    auto issue = [&](int kc, int s) {
        const int k0 = kc * 64;
        #pragma unroll
        for (int it = 0; it < 4; it++) {
            int idx = it*128 + tid;
            int row = idx >> 3, u = idx & 7;
            size_t src = (size_t)(r0 + row) * E_ + k0 + u*8;
            cp16(Xh + s*PX_ + row*72 + u*8, gx_h + src);
            cp16(Xl + s*PX_ + row*72 + u*8, gx_l + src);
        }
        #pragma unroll
        for (int it = 0; it < 8; it++) {
            int idx = it*128 + tid;
            int row = idx >> 4, u = idx & 15;
            size_t src = (size_t)(k0 + row) * H_ + u*8;
            cp16(Wh + s*PW_ + row*136 + u*8, wh + src);
            cp16(Wl + s*PW_ + row*136 + u*8, wl + src);
        }
        cp_commit();
    };

    float acc[16][4];
    #pragma unroll
    for (int f = 0; f < 16; f++)
        #pragma unroll
        for (int e = 0; e < 4; e++) acc[f][e] = 0.f;

    issue(0, 0);

    for (int kc = 0; kc < 16; kc++) {
        const int s = kc & 1;
        if (kc < 15) { issue(kc+1, s^1); cp_wait<1>(); }
        else         { cp_wait<0>(); }
        __syncthreads();

        const __nv_bfloat16* xh = Xh + s*PX_;
        const __nv_bfloat16* xl = Xl + s*PX_;
        const __nv_bfloat16* whs = Wh + s*PW_;
        const __nv_bfloat16* wls = Wl + s*PW_;

        #pragma unroll
        for (int kk = 0; kk < 4; kk++) {
            uint32_t ah[4], al[4];
            const int arow = 16*wrp + (lane & 15);
            const int acol = kk*16 + (lane >> 4) * 8;
            ldm_x4(ah, xh + arow*72 + acol);
            ldm_x4(al, xl + arow*72 + acol);
            #pragma unroll
            for (int fp = 0; fp < 8; fp++) {
                uint32_t bh[4], bl[4];
                const int brow = kk*16 + (lane & 7) + ((lane >> 3) & 1) * 8;
                const int bcol = fp*16 + ((lane >> 4) & 1) * 8;
                ldm_x4_t(bh, whs + brow*136 + bcol);
                ldm_x4_t(bl, wls + brow*136 + bcol);
                mma16816(acc[2*fp],   ah, &bh[0]);
                mma16816(acc[2*fp],   ah, &bl[0]);
                mma16816(acc[2*fp],   al, &bh[0]);
                mma16816(acc[2*fp+1], ah, &bh[2]);
                mma16816(acc[2*fp+1], ah, &bl[2]);
                mma16816(acc[2*fp+1], al, &bh[2]);
            }
        }
        __syncthreads();
    }

    const float scale = (mat == 0) ? 0.08838834764831845f : 1.0f;
    const int row0 = r0 + wrp*16 + g;
    const int row1 = row0 + 8;
    #pragma unroll
    for (int f = 0; f < 16; f++) {
        const int col = f*8 + tg*2;
        float v0 = acc[f][0]*scale, v1 = acc[f][1]*scale;
        float v2 = acc[f][2]*scale, v3 = acc[f][3]*scale;
        *reinterpret_cast<uint32_t*>(oh + (size_t)row0*H_ + col) = pack_hi2(v0, v1);
        *reinterpret_cast<uint32_t*>(ol + (size_t)row0*H_ + col) = pack_lo2(v0, v1);
        *reinterpret_cast<uint32_t*>(oh + (size_t)row1*H_ + col) = pack_hi2(v2, v3);
        *reinterpret_cast<uint32_t*>(ol + (size_t)row1*H_ + col) = pack_lo2(v2, v3);
    }
}

// ---------------------------------------------------------------------------
// Flash attention: 64 q-rows, 4 warps, KV tiles of 32, 2-stage cp.async,
// smem 104.4 KB -> 2 CTAs/SM.
// ---------------------------------------------------------------------------
#define AQ_ (64*136)
#define AK_ (32*136)

__global__ __launch_bounds__(128, 2) void attn_mma(float* __restrict__ out)
{
    extern __shared__ __nv_bfloat16 sma[];
    __nv_bfloat16* Qh = sma;               // [64*136]
    __nv_bfloat16* Ql = Qh + AQ_;
    __nv_bfloat16* Kh = Ql + AQ_;          // [2][32*136]
    __nv_bfloat16* Kl = Kh + 2*AK_;
    __nv_bfloat16* Vh = Kl + 2*AK_;
    __nv_bfloat16* Vl = Vh + 2*AK_;

    const int b    = blockIdx.y;
    const int qi   = (int)gridDim.x - 1 - (int)blockIdx.x;  // longest first
    const int q0   = qi * 64;
    const int jmax = 2*qi + 1;
    const int tid  = threadIdx.x;
    const int wrp  = tid >> 5;
    const int lane = tid & 31;
    const int g    = lane >> 2;
    const int tg   = lane & 3;

    auto issue_kv = [&](int j, int s) {
        const __nv_bfloat16* kh = gk_h + (size_t)(b*T_ + j*32) * H_;
        const __nv_bfloat16* kl = gk_l + (size_t)(b*T_ + j*32) * H_;
        const __nv_bfloat16* vh = gv_h + (size_t)(b*T_ + j*32) * H_;
        const __nv_bfloat16* vl = gv_l + (size_t)(b*T_ + j*32) * H_;
        #pragma unroll
        for (int it = 0; it < 4; it++) {
            int idx = it*128 + tid;
            int row = idx >> 4, u = idx & 15;
            int d = row*136 + u*8;
            size_t src = (size_t)row*H_ + u*8;
            cp16(Kh + s*AK_ + d, kh + src);
            cp16(Kl + s*AK_ + d, kl + src);
            cp16(Vh + s*AK_ + d, vh + src);
            cp16(Vl + s*AK_ + d, vl + src);
        }
        cp_commit();
    };

    // prologue: Q + KV stage 0
    {
        const __nv_bfloat16* qh = gq_h + (size_t)(b*T_ + q0) * H_;
        const __nv_bfloat16* ql = gq_l + (size_t)(b*T_ + q0) * H_;
        #pragma unroll
        for (int it = 0; it < 8; it++) {
            int idx = it*128 + tid;
            int row = idx >> 4, u = idx & 15;
            int d = row*136 + u*8;
            size_t src = (size_t)row*H_ + u*8;
            cp16(Qh + d, qh + src);
            cp16(Ql + d, ql + src);
        }
        const __nv_bfloat16* kh = gk_h + (size_t)(b*T_) * H_;
        const __nv_bfloat16* kl = gk_l + (size_t)(b*T_) * H_;
        const __nv_bfloat16* vh = gv_h + (size_t)(b*T_) * H_;
        const __nv_bfloat16* vl = gv_l + (size_t)(b*T_) * H_;
        #pragma unroll
        for (int it = 0; it < 4; it++) {
            int idx = it*128 + tid;
            int row = idx >> 4, u = idx & 15;
            int d = row*136 + u*8;
            size_t src = (size_t)row*H_ + u*8;
            cp16(Kh + d, kh + src);
            cp16(Kl + d, kl + src);
            cp16(Vh + d, vh + src);
            cp16(Vl + d, vl + src);
        }
        cp_commit();
    }

    float o[16][4];
    #pragma unroll
    for (int f = 0; f < 16; f++)
        #pragma unroll
        for (int e = 0; e < 4; e++) o[f][e] = 0.f;
    float m0 = -1e30f, m1 = -1e30f, l0 = 0.f, l1 = 0.f;

    for (int j = 0; j <= jmax; j++) {
        const int s = j & 1;
        if (j < jmax) { issue_kv(j+1, s^1); cp_wait<1>(); }
        else          { cp_wait<0>(); }
        __syncthreads();

        const __nv_bfloat16* kh = Kh + s*AK_;
        const __nv_bfloat16* kl = Kl + s*AK_;
        const __nv_bfloat16* vh = Vh + s*AK_;
        const __nv_bfloat16* vl = Vl + s*AK_;

        // ---- S = Q @ K^T  (64 x 32 x 128) ----
        float sv[4][4];
        #pragma unroll
        for (int f = 0; f < 4; f++)
            #pragma unroll
            for (int e = 0; e < 4; e++) sv[f][e] = 0.f;

        #pragma unroll
        for (int kk = 0; kk < 8; kk++) {
            uint32_t ah[4], al[4];
            const int arow = 16*wrp + (lane & 15);
            const int acol = kk*16 + (lane >> 4) * 8;
            ldm_x4(ah, Qh + arow*136 + acol);
            ldm_x4(al, Ql + arow*136 + acol);
            #pragma unroll
            for (int fp = 0; fp < 2; fp++) {
                uint32_t bh[4], bl[4];
                const int brow = fp*16 + (lane & 7) + ((lane >> 4) & 1) * 8;
                const int bcol = kk*16 + ((lane >> 3) & 1) * 8;
                ldm_x4(bh, kh + brow*136 + bcol);
                ldm_x4(bl, kl + brow*136 + bcol);
                mma16816(sv[2*fp],   ah, &bh[0]);
                mma16816(sv[2*fp],   ah, &bl[0]);
                mma16816(sv[2*fp],   al, &bh[0]);
                mma16816(sv[2*fp+1], ah, &bh[2]);
                mma16816(sv[2*fp+1], ah, &bl[2]);
                mma16816(sv[2*fp+1], al, &bh[2]);
            }
        }

        // ---- causal mask (last two KV tiles) ----
        if (j >= 2*qi) {
            #pragma unroll
            for (int f = 0; f < 4; f++) {
                #pragma unroll
                for (int e = 0; e < 4; e++) {
                    int colg = j*32 + f*8 + tg*2 + (e & 1);
                    int rowg = q0 + wrp*16 + g + ((e >> 1) ? 8 : 0);
                    if (colg > rowg) sv[f][e] = -1e30f;
                }
            }
        }

        // ---- online softmax ----
        float rm0 = -1e30f, rm1 = -1e30f;
        #pragma unroll
        for (int f = 0; f < 4; f++) {
            rm0 = fmaxf(rm0, fmaxf(sv[f][0], sv[f][1]));
            rm1 = fmaxf(rm1, fmaxf(sv[f][2], sv[f][3]));
        }
        rm0 = fmaxf(rm0, __shfl_xor_sync(0xffffffffu, rm0, 1));
        rm0 = fmaxf(rm0, __shfl_xor_sync(0xffffffffu, rm0, 2));
        rm1 = fmaxf(rm1, __shfl_xor_sync(0xffffffffu, rm1, 1));
        rm1 = fmaxf(rm1, __shfl_xor_sync(0xffffffffu, rm1, 2));
        const float mn0 = fmaxf(m0, rm0), mn1 = fmaxf(m1, rm1);
        const float c0 = __expf(m0 - mn0), c1 = __expf(m1 - mn1);
        float ls0 = 0.f, ls1 = 0.f;
        #pragma unroll
        for (int f = 0; f < 4; f++) {
            sv[f][0] = __expf(sv[f][0] - mn0);
            sv[f][1] = __expf(sv[f][1] - mn0);
            sv[f][2] = __expf(sv[f][2] - mn1);
            sv[f][3] = __expf(sv[f][3] - mn1);
            ls0 += sv[f][0] + sv[f][1];
            ls1 += sv[f][2] + sv[f][3];
        }
        ls0 += __shfl_xor_sync(0xffffffffu, ls0, 1);
        ls0 += __shfl_xor_sync(0xffffffffu, ls0, 2);
        ls1 += __shfl_xor_sync(0xffffffffu, ls1, 1);
        ls1 += __shfl_xor_sync(0xffffffffu, ls1, 2);
        l0 = l0*c0 + ls0; l1 = l1*c1 + ls1;
        m0 = mn0; m1 = mn1;

        // Skip O rescale when no lane in the warp saw a new max.
        const bool noscale = (c0 == 1.0f) & (c1 == 1.0f);
        if (!__all_sync(0xffffffffu, noscale)) {
            #pragma unroll
            for (int f = 0; f < 16; f++) {
                o[f][0] *= c0; o[f][1] *= c0;
                o[f][2] *= c1; o[f][3] *= c1;
            }
        }

        // ---- O += P @ V  (64 x 128 x 32) ----
        #pragma unroll
        for (int kk = 0; kk < 2; kk++) {
            uint32_t ah[4], al[4];
            ah[0] = pack_hi2(sv[2*kk][0],   sv[2*kk][1]);
            ah[1] = pack_hi2(sv[2*kk][2],   sv[2*kk][3]);
            ah[2] = pack_hi2(sv[2*kk+1][0], sv[2*kk+1][1]);
            ah[3] = pack_hi2(sv[2*kk+1][2], sv[2*kk+1][3]);
            al[0] = pack_lo2(sv[2*kk][0],   sv[2*kk][1]);
            al[1] = pack_lo2(sv[2*kk][2],   sv[2*kk][3]);
            al[2] = pack_lo2(sv[2*kk+1][0], sv[2*kk+1][1]);
            al[3] = pack_lo2(sv[2*kk+1][2], sv[2*kk+1][3]);
            #pragma unroll
            for (int fp = 0; fp < 8; fp++) {
                uint32_t bh[4], bl[4];
                const int brow = kk*16 + (lane & 7) + ((lane >> 3) & 1) * 8;
                const int bcol = fp*16 + ((lane >> 4) & 1) * 8;
                ldm_x4_t(bh, vh + brow*136 + bcol);
                ldm_x4_t(bl, vl + brow*136 + bcol);
                mma16816(o[2*fp],   ah, &bh[0]);
                mma16816(o[2*fp],   ah, &bl[0]);
                mma16816(o[2*fp],   al, &bh[0]);
                mma16816(o[2*fp+1], ah, &bh[2]);
                mma16816(o[2*fp+1], ah, &bl[2]);
                mma16816(o[2*fp+1], al, &bh[2]);
            }
        }
        __syncthreads();
    }

    // ---- epilogue ----
    const float inv0 = 1.0f / l0, inv1 = 1.0f / l1;
    const size_t row0 = (size_t)b*T_ + q0 + wrp*16 + g;
    const size_t row1 = row0 + 8;
    #pragma unroll
    for (int f = 0; f < 16; f++) {
        const int col = f*8 + tg*2;
        float2 v0 = make_float2(o[f][0]*inv0, o[f][1]*inv0);
        float2 v1 = make_float2(o[f][2]*inv1, o[f][3]*inv1);
        *reinterpret_cast<float2*>(out + row0*H_ + col) = v0;
        *reinterpret_cast<float2*>(out + row1*H_ + col) = v1;
    }
}

extern "C" void kernel_launch(void* const* d_in, const int* in_sizes, int n_in,
                              void* d_out, int out_size)
{
    const float* x  = (const float*)d_in[0];
    const float* Wq = (const float*)d_in[1];
    const float* Wk = (const float*)d_in[2];
    const float* Wv = (const float*)d_in[3];
    float* out = (float*)d_out;

    const int proj_smem = (4*PX_ + 4*PW_) * (int)sizeof(__nv_bfloat16);    // 106496
    const int attn_smem = (2*AQ_ + 8*AK_) * (int)sizeof(__nv_bfloat16);    // 104448
    cudaFuncSetAttribute(proj_mma, cudaFuncAttributeMaxDynamicSharedMemorySize, proj_smem);
    cudaFuncSetAttribute(attn_mma, cudaFuncAttributeMaxDynamicSharedMemorySize, attn_smem);

    split_x_kernel<<<BT_*E_/4/256, 256>>>(x);
    split_w_kernel<<<dim3(E_*H_/4/256, 3), 256>>>(Wq, Wk, Wv);
    proj_mma<<<dim3(BT_/64, 3), 128, proj_smem>>>();
    attn_mma<<<dim3(T_/64, B_), 128, attn_smem>>>(out);
}

// round 8
// speedup vs baseline: 1.0934x; 1.0934x over previous
#include <cuda_runtime.h>
#include <cuda_bf16.h>
#include <stdint.h>

#define B_  8
#define T_  2048
#define E_  1024
#define H_  128
#define BT_ (B_*T_)

// ---- global scratch ----
__device__ __nv_bfloat16 gx_h[BT_*E_];
__device__ __nv_bfloat16 gx_l[BT_*E_];
__device__ __nv_bfloat16 gw_h[3][E_*H_];
__device__ __nv_bfloat16 gw_l[3][E_*H_];
__device__ __nv_bfloat16 gq_h[BT_*H_];
__device__ __nv_bfloat16 gq_l[BT_*H_];
__device__ __nv_bfloat16 gk_h[BT_*H_];
__device__ __nv_bfloat16 gk_l[BT_*H_];
__device__ __nv_bfloat16 gv_h[BT_*H_];
__device__ __nv_bfloat16 gv_l[BT_*H_];

// ---- helpers ----
__device__ __forceinline__ void ldm_x4(uint32_t* r, const void* p) {
    uint32_t a = (uint32_t)__cvta_generic_to_shared(p);
    asm volatile("ldmatrix.sync.aligned.m8n8.x4.shared.b16 {%0,%1,%2,%3}, [%4];"
                 : "=r"(r[0]), "=r"(r[1]), "=r"(r[2]), "=r"(r[3]) : "r"(a));
}
__device__ __forceinline__ void ldm_x4_t(uint32_t* r, const void* p) {
    uint32_t a = (uint32_t)__cvta_generic_to_shared(p);
    asm volatile("ldmatrix.sync.aligned.m8n8.x4.trans.shared.b16 {%0,%1,%2,%3}, [%4];"
                 : "=r"(r[0]), "=r"(r[1]), "=r"(r[2]), "=r"(r[3]) : "r"(a));
}
__device__ __forceinline__ void mma16816(float* d, const uint32_t* a, const uint32_t* b) {
    asm volatile("mma.sync.aligned.m16n8k16.row.col.f32.bf16.bf16.f32 "
                 "{%0,%1,%2,%3}, {%4,%5,%6,%7}, {%8,%9}, {%0,%1,%2,%3};"
                 : "+f"(d[0]), "+f"(d[1]), "+f"(d[2]), "+f"(d[3])
                 : "r"(a[0]), "r"(a[1]), "r"(a[2]), "r"(a[3]), "r"(b[0]), "r"(b[1]));
}
__device__ __forceinline__ uint32_t pack_hi2(float a, float b) {
    __nv_bfloat162 h;
    h.x = __float2bfloat16_rn(a);
    h.y = __float2bfloat16_rn(b);
    return *reinterpret_cast<uint32_t*>(&h);
}
__device__ __forceinline__ uint32_t pack_lo2(float a, float b) {
    __nv_bfloat16 ha = __float2bfloat16_rn(a);
    __nv_bfloat16 hb = __float2bfloat16_rn(b);
    __nv_bfloat162 l;
    l.x = __float2bfloat16_rn(a - __bfloat162float(ha));
    l.y = __float2bfloat16_rn(b - __bfloat162float(hb));
    return *reinterpret_cast<uint32_t*>(&l);
}
__device__ __forceinline__ void cp16(void* smem, const void* gmem) {
    uint32_t a = (uint32_t)__cvta_generic_to_shared(smem);
    asm volatile("cp.async.cg.shared.global [%0], [%1], 16;" :: "r"(a), "l"(gmem));
}
__device__ __forceinline__ void cp_commit() { asm volatile("cp.async.commit_group;"); }
template<int N> __device__ __forceinline__ void cp_wait() {
    asm volatile("cp.async.wait_group %0;" :: "n"(N));
}

// ---------------------------------------------------------------------------
// Split kernels
// ---------------------------------------------------------------------------
__global__ void split_x_kernel(const float* __restrict__ x)
{
    int i = blockIdx.x * 256 + threadIdx.x;
    float4 v = reinterpret_cast<const float4*>(x)[i];
    uint2 hv, lv;
    hv.x = pack_hi2(v.x, v.y); hv.y = pack_hi2(v.z, v.w);
    lv.x = pack_lo2(v.x, v.y); lv.y = pack_lo2(v.z, v.w);
    reinterpret_cast<uint2*>(gx_h)[i] = hv;
    reinterpret_cast<uint2*>(gx_l)[i] = lv;
}

__global__ void split_w_kernel(const float* __restrict__ Wq,
                               const float* __restrict__ Wk,
                               const float* __restrict__ Wv)
{
    const float* W = (blockIdx.y == 0) ? Wq : (blockIdx.y == 1) ? Wk : Wv;
    __nv_bfloat16* oh = gw_h[blockIdx.y];
    __nv_bfloat16* ol = gw_l[blockIdx.y];
    int i = blockIdx.x * 256 + threadIdx.x;
    float4 v = reinterpret_cast<const float4*>(W)[i];
    uint2 hv, lv;
    hv.x = pack_hi2(v.x, v.y); hv.y = pack_hi2(v.z, v.w);
    lv.x = pack_lo2(v.x, v.y); lv.y = pack_lo2(v.z, v.w);
    reinterpret_cast<uint2*>(oh)[i] = hv;
    reinterpret_cast<uint2*>(ol)[i] = lv;
}

// ---------------------------------------------------------------------------
// Projection: 64x128 tile, BK=64, 4 warps, 2-stage cp.async, term-major MMAs.
// ---------------------------------------------------------------------------
#define PX_ (64*72)
#define PW_ (64*136)

__global__ __launch_bounds__(128, 2) void proj_mma()
{
    extern __shared__ __nv_bfloat16 smp[];
    __nv_bfloat16* Xh = smp;               // [2][64*72]
    __nv_bfloat16* Xl = Xh + 2*PX_;
    __nv_bfloat16* Wh = Xl + 2*PX_;        // [2][64*136]
    __nv_bfloat16* Wl = Wh + 2*PW_;

    const int mat = blockIdx.y;
    const __nv_bfloat16* wh = gw_h[mat];
    const __nv_bfloat16* wl = gw_l[mat];
    __nv_bfloat16 *oh, *ol;
    if (mat == 0)      { oh = gq_h; ol = gq_l; }
    else if (mat == 1) { oh = gk_h; ol = gk_l; }
    else               { oh = gv_h; ol = gv_l; }

    const int r0   = blockIdx.x * 64;
    const int tid  = threadIdx.x;
    const int wrp  = tid >> 5;
    const int lane = tid & 31;
    const int g    = lane >> 2;
    const int tg   = lane & 3;

    auto issue = [&](int kc, int s) {
        const int k0 = kc * 64;
        #pragma unroll
        for (int it = 0; it < 4; it++) {
            int idx = it*128 + tid;
            int row = idx >> 3, u = idx & 7;
            size_t src = (size_t)(r0 + row) * E_ + k0 + u*8;
            cp16(Xh + s*PX_ + row*72 + u*8, gx_h + src);
            cp16(Xl + s*PX_ + row*72 + u*8, gx_l + src);
        }
        #pragma unroll
        for (int it = 0; it < 8; it++) {
            int idx = it*128 + tid;
            int row = idx >> 4, u = idx & 15;
            size_t src = (size_t)(k0 + row) * H_ + u*8;
            cp16(Wh + s*PW_ + row*136 + u*8, wh + src);
            cp16(Wl + s*PW_ + row*136 + u*8, wl + src);
        }
        cp_commit();
    };

    float acc[16][4];
    #pragma unroll
    for (int f = 0; f < 16; f++)
        #pragma unroll
        for (int e = 0; e < 4; e++) acc[f][e] = 0.f;

    issue(0, 0);

    for (int kc = 0; kc < 16; kc++) {
        const int s = kc & 1;
        if (kc < 15) { issue(kc+1, s^1); cp_wait<1>(); }
        else         { cp_wait<0>(); }
        __syncthreads();

        const __nv_bfloat16* xh = Xh + s*PX_;
        const __nv_bfloat16* xl = Xl + s*PX_;
        const __nv_bfloat16* whs = Wh + s*PW_;
        const __nv_bfloat16* wls = Wl + s*PW_;

        #pragma unroll
        for (int kk = 0; kk < 4; kk++) {
            uint32_t ah[4], al[4];
            const int arow = 16*wrp + (lane & 15);
            const int acol = kk*16 + (lane >> 4) * 8;
            ldm_x4(ah, xh + arow*72 + acol);
            ldm_x4(al, xl + arow*72 + acol);
            const int brow = kk*16 + (lane & 7) + ((lane >> 3) & 1) * 8;

            #pragma unroll
            for (int hf = 0; hf < 2; hf++) {
                uint32_t bh[4][4], bl[4][4];
                #pragma unroll
                for (int i = 0; i < 4; i++) {
                    const int bcol = (hf*4 + i)*16 + ((lane >> 4) & 1) * 8;
                    ldm_x4_t(bh[i], whs + brow*136 + bcol);
                    ldm_x4_t(bl[i], wls + brow*136 + bcol);
                }
                // term-major: hh, hl, lh — accumulator updates 8 MMAs apart
                #pragma unroll
                for (int i = 0; i < 4; i++) {
                    const int fp = hf*4 + i;
                    mma16816(acc[2*fp],   ah, &bh[i][0]);
                    mma16816(acc[2*fp+1], ah, &bh[i][2]);
                }
                #pragma unroll
                for (int i = 0; i < 4; i++) {
                    const int fp = hf*4 + i;
                    mma16816(acc[2*fp],   ah, &bl[i][0]);
                    mma16816(acc[2*fp+1], ah, &bl[i][2]);
                }
                #pragma unroll
                for (int i = 0; i < 4; i++) {
                    const int fp = hf*4 + i;
                    mma16816(acc[2*fp],   al, &bh[i][0]);
                    mma16816(acc[2*fp+1], al, &bh[i][2]);
                }
            }
        }
        __syncthreads();
    }

    const float scale = (mat == 0) ? 0.08838834764831845f : 1.0f;
    const int row0 = r0 + wrp*16 + g;
    const int row1 = row0 + 8;
    #pragma unroll
    for (int f = 0; f < 16; f++) {
        const int col = f*8 + tg*2;
        float v0 = acc[f][0]*scale, v1 = acc[f][1]*scale;
        float v2 = acc[f][2]*scale, v3 = acc[f][3]*scale;
        *reinterpret_cast<uint32_t*>(oh + (size_t)row0*H_ + col) = pack_hi2(v0, v1);
        *reinterpret_cast<uint32_t*>(ol + (size_t)row0*H_ + col) = pack_lo2(v0, v1);
        *reinterpret_cast<uint32_t*>(oh + (size_t)row1*H_ + col) = pack_hi2(v2, v3);
        *reinterpret_cast<uint32_t*>(ol + (size_t)row1*H_ + col) = pack_lo2(v2, v3);
    }
}

// ---------------------------------------------------------------------------
// Flash attention: 64 q-rows, 4 warps, KV tiles of 64, 2-stage cp.async,
// term-major MMAs.
// ---------------------------------------------------------------------------
#define AQ_ (64*136)
#define AK_ (64*136)

__global__ __launch_bounds__(128, 1) void attn_mma(float* __restrict__ out)
{
    extern __shared__ __nv_bfloat16 sma[];
    __nv_bfloat16* Qh = sma;               // [64*136]
    __nv_bfloat16* Ql = Qh + AQ_;
    __nv_bfloat16* Kh = Ql + AQ_;          // [2][64*136]
    __nv_bfloat16* Kl = Kh + 2*AK_;
    __nv_bfloat16* Vh = Kl + 2*AK_;
    __nv_bfloat16* Vl = Vh + 2*AK_;

    const int b    = blockIdx.y;
    const int qi   = (int)gridDim.x - 1 - (int)blockIdx.x;  // longest first
    const int q0   = qi * 64;
    const int tid  = threadIdx.x;
    const int wrp  = tid >> 5;
    const int lane = tid & 31;
    const int g    = lane >> 2;
    const int tg   = lane & 3;

    auto issue_kv = [&](int j, int s) {
        const __nv_bfloat16* kh = gk_h + (size_t)(b*T_ + j*64) * H_;
        const __nv_bfloat16* kl = gk_l + (size_t)(b*T_ + j*64) * H_;
        const __nv_bfloat16* vh = gv_h + (size_t)(b*T_ + j*64) * H_;
        const __nv_bfloat16* vl = gv_l + (size_t)(b*T_ + j*64) * H_;
        #pragma unroll
        for (int it = 0; it < 8; it++) {
            int idx = it*128 + tid;
            int row = idx >> 4, u = idx & 15;
            int d = row*136 + u*8;
            size_t src = (size_t)row*H_ + u*8;
            cp16(Kh + s*AK_ + d, kh + src);
            cp16(Kl + s*AK_ + d, kl + src);
            cp16(Vh + s*AK_ + d, vh + src);
            cp16(Vl + s*AK_ + d, vl + src);
        }
        cp_commit();
    };

    // prologue: Q + KV stage 0
    {
        const __nv_bfloat16* qh = gq_h + (size_t)(b*T_ + q0) * H_;
        const __nv_bfloat16* ql = gq_l + (size_t)(b*T_ + q0) * H_;
        #pragma unroll
        for (int it = 0; it < 8; it++) {
            int idx = it*128 + tid;
            int row = idx >> 4, u = idx & 15;
            int d = row*136 + u*8;
            size_t src = (size_t)row*H_ + u*8;
            cp16(Qh + d, qh + src);
            cp16(Ql + d, ql + src);
        }
        const __nv_bfloat16* kh = gk_h + (size_t)(b*T_) * H_;
        const __nv_bfloat16* kl = gk_l + (size_t)(b*T_) * H_;
        const __nv_bfloat16* vh = gv_h + (size_t)(b*T_) * H_;
        const __nv_bfloat16* vl = gv_l + (size_t)(b*T_) * H_;
        #pragma unroll
        for (int it = 0; it < 8; it++) {
            int idx = it*128 + tid;
            int row = idx >> 4, u = idx & 15;
            int d = row*136 + u*8;
            size_t src = (size_t)row*H_ + u*8;
            cp16(Kh + d, kh + src);
            cp16(Kl + d, kl + src);
            cp16(Vh + d, vh + src);
            cp16(Vl + d, vl + src);
        }
        cp_commit();
    }

    float o[16][4];
    #pragma unroll
    for (int f = 0; f < 16; f++)
        #pragma unroll
        for (int e = 0; e < 4; e++) o[f][e] = 0.f;
    float m0 = -1e30f, m1 = -1e30f, l0 = 0.f, l1 = 0.f;

    for (int j = 0; j <= qi; j++) {
        const int s = j & 1;
        if (j < qi) { issue_kv(j+1, s^1); cp_wait<1>(); }
        else        { cp_wait<0>(); }
        __syncthreads();

        const __nv_bfloat16* kh = Kh + s*AK_;
        const __nv_bfloat16* kl = Kl + s*AK_;
        const __nv_bfloat16* vh = Vh + s*AK_;
        const __nv_bfloat16* vl = Vl + s*AK_;

        // ---- S = Q @ K^T  (64 x 64 x 128), term-major ----
        float sv[8][4];
        #pragma unroll
        for (int f = 0; f < 8; f++)
            #pragma unroll
            for (int e = 0; e < 4; e++) sv[f][e] = 0.f;

        #pragma unroll
        for (int kk = 0; kk < 8; kk++) {
            uint32_t ah[4], al[4];
            const int arow = 16*wrp + (lane & 15);
            const int acol = kk*16 + (lane >> 4) * 8;
            ldm_x4(ah, Qh + arow*136 + acol);
            ldm_x4(al, Ql + arow*136 + acol);

            uint32_t bh[4][4], bl[4][4];
            #pragma unroll
            for (int fp = 0; fp < 4; fp++) {
                const int brow = fp*16 + (lane & 7) + ((lane >> 4) & 1) * 8;
                const int bcol = kk*16 + ((lane >> 3) & 1) * 8;
                ldm_x4(bh[fp], kh + brow*136 + bcol);
                ldm_x4(bl[fp], kl + brow*136 + bcol);
            }
            #pragma unroll
            for (int fp = 0; fp < 4; fp++) {
                mma16816(sv[2*fp],   ah, &bh[fp][0]);
                mma16816(sv[2*fp+1], ah, &bh[fp][2]);
            }
            #pragma unroll
            for (int fp = 0; fp < 4; fp++) {
                mma16816(sv[2*fp],   ah, &bl[fp][0]);
                mma16816(sv[2*fp+1], ah, &bl[fp][2]);
            }
            #pragma unroll
            for (int fp = 0; fp < 4; fp++) {
                mma16816(sv[2*fp],   al, &bh[fp][0]);
                mma16816(sv[2*fp+1], al, &bh[fp][2]);
            }
        }

        // ---- causal mask on diagonal tile ----
        if (j == qi) {
            #pragma unroll
            for (int f = 0; f < 8; f++) {
                #pragma unroll
                for (int e = 0; e < 4; e++) {
                    int col = f*8 + tg*2 + (e & 1);
                    int row = wrp*16 + g + ((e >> 1) ? 8 : 0);
                    if (col > row) sv[f][e] = -1e30f;
                }
            }
        }

        // ---- online softmax ----
        float rm0 = -1e30f, rm1 = -1e30f;
        #pragma unroll
        for (int f = 0; f < 8; f++) {
            rm0 = fmaxf(rm0, fmaxf(sv[f][0], sv[f][1]));
            rm1 = fmaxf(rm1, fmaxf(sv[f][2], sv[f][3]));
        }
        rm0 = fmaxf(rm0, __shfl_xor_sync(0xffffffffu, rm0, 1));
        rm0 = fmaxf(rm0, __shfl_xor_sync(0xffffffffu, rm0, 2));
        rm1 = fmaxf(rm1, __shfl_xor_sync(0xffffffffu, rm1, 1));
        rm1 = fmaxf(rm1, __shfl_xor_sync(0xffffffffu, rm1, 2));
        const float mn0 = fmaxf(m0, rm0), mn1 = fmaxf(m1, rm1);
        const float c0 = __expf(m0 - mn0), c1 = __expf(m1 - mn1);
        float ls0 = 0.f, ls1 = 0.f;
        #pragma unroll
        for (int f = 0; f < 8; f++) {
            sv[f][0] = __expf(sv[f][0] - mn0);
            sv[f][1] = __expf(sv[f][1] - mn0);
            sv[f][2] = __expf(sv[f][2] - mn1);
            sv[f][3] = __expf(sv[f][3] - mn1);
            ls0 += sv[f][0] + sv[f][1];
            ls1 += sv[f][2] + sv[f][3];
        }
        ls0 += __shfl_xor_sync(0xffffffffu, ls0, 1);
        ls0 += __shfl_xor_sync(0xffffffffu, ls0, 2);
        ls1 += __shfl_xor_sync(0xffffffffu, ls1, 1);
        ls1 += __shfl_xor_sync(0xffffffffu, ls1, 2);
        l0 = l0*c0 + ls0; l1 = l1*c1 + ls1;
        m0 = mn0; m1 = mn1;

        const bool noscale = (c0 == 1.0f) & (c1 == 1.0f);
        if (!__all_sync(0xffffffffu, noscale)) {
            #pragma unroll
            for (int f = 0; f < 16; f++) {
                o[f][0] *= c0; o[f][1] *= c0;
                o[f][2] *= c1; o[f][3] *= c1;
            }
        }

        // ---- O += P @ V  (64 x 128 x 64), term-major per half ----
        #pragma unroll
        for (int kk = 0; kk < 4; kk++) {
            uint32_t ah[4], al[4];
            ah[0] = pack_hi2(sv[2*kk][0],   sv[2*kk][1]);
            ah[1] = pack_hi2(sv[2*kk][2],   sv[2*kk][3]);
            ah[2] = pack_hi2(sv[2*kk+1][0], sv[2*kk+1][1]);
            ah[3] = pack_hi2(sv[2*kk+1][2], sv[2*kk+1][3]);
            al[0] = pack_lo2(sv[2*kk][0],   sv[2*kk][1]);
            al[1] = pack_lo2(sv[2*kk][2],   sv[2*kk][3]);
            al[2] = pack_lo2(sv[2*kk+1][0], sv[2*kk+1][1]);
            al[3] = pack_lo2(sv[2*kk+1][2], sv[2*kk+1][3]);
            const int brow = kk*16 + (lane & 7) + ((lane >> 3) & 1) * 8;

            #pragma unroll
            for (int hf = 0; hf < 2; hf++) {
                uint32_t bh[4][4], bl[4][4];
                #pragma unroll
                for (int i = 0; i < 4; i++) {
                    const int bcol = (hf*4 + i)*16 + ((lane >> 4) & 1) * 8;
                    ldm_x4_t(bh[i], vh + brow*136 + bcol);
                    ldm_x4_t(bl[i], vl + brow*136 + bcol);
                }
                #pragma unroll
                for (int i = 0; i < 4; i++) {
                    const int fp = hf*4 + i;
                    mma16816(o[2*fp],   ah, &bh[i][0]);
                    mma16816(o[2*fp+1], ah, &bh[i][2]);
                }
                #pragma unroll
                for (int i = 0; i < 4; i++) {
                    const int fp = hf*4 + i;
                    mma16816(o[2*fp],   ah, &bl[i][0]);
                    mma16816(o[2*fp+1], ah, &bl[i][2]);
                }
                #pragma unroll
                for (int i = 0; i < 4; i++) {
                    const int fp = hf*4 + i;
                    mma16816(o[2*fp],   al, &bh[i][0]);
                    mma16816(o[2*fp+1], al, &bh[i][2]);
                }
            }
        }
        __syncthreads();
    }

    // ---- epilogue ----
    const float inv0 = 1.0f / l0, inv1 = 1.0f / l1;
    const size_t row0 = (size_t)b*T_ + q0 + wrp*16 + g;
    const size_t row1 = row0 + 8;
    #pragma unroll
    for (int f = 0; f < 16; f++) {
        const int col = f*8 + tg*2;
        float2 v0 = make_float2(o[f][0]*inv0, o[f][1]*inv0);
        float2 v1 = make_float2(o[f][2]*inv1, o[f][3]*inv1);
        *reinterpret_cast<float2*>(out + row0*H_ + col) = v0;
        *reinterpret_cast<float2*>(out + row1*H_ + col) = v1;
    }
}

extern "C" void kernel_launch(void* const* d_in, const int* in_sizes, int n_in,
                              void* d_out, int out_size)
{
    const float* x  = (const float*)d_in[0];
    const float* Wq = (const float*)d_in[1];
    const float* Wk = (const float*)d_in[2];
    const float* Wv = (const float*)d_in[3];
    float* out = (float*)d_out;

    const int proj_smem = (4*PX_ + 4*PW_) * (int)sizeof(__nv_bfloat16);    // 106496
    const int attn_smem = (2*AQ_ + 8*AK_) * (int)sizeof(__nv_bfloat16);    // 174080
    cudaFuncSetAttribute(proj_mma, cudaFuncAttributeMaxDynamicSharedMemorySize, proj_smem);
    cudaFuncSetAttribute(attn_mma, cudaFuncAttributeMaxDynamicSharedMemorySize, attn_smem);

    split_x_kernel<<<BT_*E_/4/256, 256>>>(x);
    split_w_kernel<<<dim3(E_*H_/4/256, 3), 256>>>(Wq, Wk, Wv);
    proj_mma<<<dim3(BT_/64, 3), 128, proj_smem>>>();
    attn_mma<<<dim3(T_/64, B_), 128, attn_smem>>>(out);
}

// round 9
// speedup vs baseline: 2.3078x; 2.1106x over previous
#include <cuda_runtime.h>
#include <cuda_fp16.h>
#include <stdint.h>

#define B_  8
#define T_  2048
#define E_  1024
#define H_  128
#define BT_ (B_*T_)

// ---- global scratch (fp16) ----
__device__ __half gx[BT_*E_];
__device__ __half gw[3][E_*H_];
__device__ __half gq[BT_*H_];
__device__ __half gk[BT_*H_];
__device__ __half gv[BT_*H_];

// ---- helpers ----
__device__ __forceinline__ void ldm_x4(uint32_t* r, const void* p) {
    uint32_t a = (uint32_t)__cvta_generic_to_shared(p);
    asm volatile("ldmatrix.sync.aligned.m8n8.x4.shared.b16 {%0,%1,%2,%3}, [%4];"
                 : "=r"(r[0]), "=r"(r[1]), "=r"(r[2]), "=r"(r[3]) : "r"(a));
}
__device__ __forceinline__ void ldm_x4_t(uint32_t* r, const void* p) {
    uint32_t a = (uint32_t)__cvta_generic_to_shared(p);
    asm volatile("ldmatrix.sync.aligned.m8n8.x4.trans.shared.b16 {%0,%1,%2,%3}, [%4];"
                 : "=r"(r[0]), "=r"(r[1]), "=r"(r[2]), "=r"(r[3]) : "r"(a));
}
__device__ __forceinline__ void mma16816(float* d, const uint32_t* a, const uint32_t* b) {
    asm volatile("mma.sync.aligned.m16n8k16.row.col.f32.f16.f16.f32 "
                 "{%0,%1,%2,%3}, {%4,%5,%6,%7}, {%8,%9}, {%0,%1,%2,%3};"
                 : "+f"(d[0]), "+f"(d[1]), "+f"(d[2]), "+f"(d[3])
                 : "r"(a[0]), "r"(a[1]), "r"(a[2]), "r"(a[3]), "r"(b[0]), "r"(b[1]));
}
__device__ __forceinline__ uint32_t pack_h2(float a, float b) {
    __half2 h;
    h.x = __float2half_rn(a);
    h.y = __float2half_rn(b);
    return *reinterpret_cast<uint32_t*>(&h);
}
__device__ __forceinline__ void cp16(void* smem, const void* gmem) {
    uint32_t a = (uint32_t)__cvta_generic_to_shared(smem);
    asm volatile("cp.async.cg.shared.global [%0], [%1], 16;" :: "r"(a), "l"(gmem));
}
__device__ __forceinline__ void cp_commit() { asm volatile("cp.async.commit_group;"); }
template<int N> __device__ __forceinline__ void cp_wait() {
    asm volatile("cp.async.wait_group %0;" :: "n"(N));
}

// ---------------------------------------------------------------------------
// Convert kernels: fp32 -> fp16
// ---------------------------------------------------------------------------
__global__ void conv_x_kernel(const float* __restrict__ x)
{
    int i = blockIdx.x * 256 + threadIdx.x;
    float4 v = reinterpret_cast<const float4*>(x)[i];
    uint2 hv;
    hv.x = pack_h2(v.x, v.y);
    hv.y = pack_h2(v.z, v.w);
    reinterpret_cast<uint2*>(gx)[i] = hv;
}

__global__ void conv_w_kernel(const float* __restrict__ Wq,
                              const float* __restrict__ Wk,
                              const float* __restrict__ Wv)
{
    const float* W = (blockIdx.y == 0) ? Wq : (blockIdx.y == 1) ? Wk : Wv;
    __half* o = gw[blockIdx.y];
    int i = blockIdx.x * 256 + threadIdx.x;
    float4 v = reinterpret_cast<const float4*>(W)[i];
    uint2 hv;
    hv.x = pack_h2(v.x, v.y);
    hv.y = pack_h2(v.z, v.w);
    reinterpret_cast<uint2*>(o)[i] = hv;
}

// ---------------------------------------------------------------------------
// Projection: 64x128 tile, BK=64, 4 warps, 2-stage cp.async, fp16 single-term.
// ---------------------------------------------------------------------------
#define PX_ (64*72)
#define PW_ (64*136)

__global__ __launch_bounds__(128, 2) void proj_mma()
{
    extern __shared__ __half smp[];
    __half* Xs = smp;               // [2][64*72]
    __half* Ws = Xs + 2*PX_;        // [2][64*136]

    const int mat = blockIdx.y;
    const __half* wp = gw[mat];
    __half* op = (mat == 0) ? gq : (mat == 1) ? gk : gv;

    const int r0   = blockIdx.x * 64;
    const int tid  = threadIdx.x;
    const int wrp  = tid >> 5;
    const int lane = tid & 31;
    const int g    = lane >> 2;
    const int tg   = lane & 3;

    auto issue = [&](int kc, int s) {
        const int k0 = kc * 64;
        #pragma unroll
        for (int it = 0; it < 4; it++) {
            int idx = it*128 + tid;
            int row = idx >> 3, u = idx & 7;
            cp16(Xs + s*PX_ + row*72 + u*8, gx + (size_t)(r0 + row) * E_ + k0 + u*8);
        }
        #pragma unroll
        for (int it = 0; it < 8; it++) {
            int idx = it*128 + tid;
            int row = idx >> 4, u = idx & 15;
            cp16(Ws + s*PW_ + row*136 + u*8, wp + (size_t)(k0 + row) * H_ + u*8);
        }
        cp_commit();
    };

    float acc[16][4];
    #pragma unroll
    for (int f = 0; f < 16; f++)
        #pragma unroll
        for (int e = 0; e < 4; e++) acc[f][e] = 0.f;

    issue(0, 0);

    for (int kc = 0; kc < 16; kc++) {
        const int s = kc & 1;
        if (kc < 15) { issue(kc+1, s^1); cp_wait<1>(); }
        else         { cp_wait<0>(); }
        __syncthreads();

        const __half* xs = Xs + s*PX_;
        const __half* ws = Ws + s*PW_;

        #pragma unroll
        for (int kk = 0; kk < 4; kk++) {
            uint32_t a[4];
            const int arow = 16*wrp + (lane & 15);
            const int acol = kk*16 + (lane >> 4) * 8;
            ldm_x4(a, xs + arow*72 + acol);
            const int brow = kk*16 + (lane & 7) + ((lane >> 3) & 1) * 8;
            #pragma unroll
            for (int fp = 0; fp < 8; fp++) {
                uint32_t bb[4];
                const int bcol = fp*16 + ((lane >> 4) & 1) * 8;
                ldm_x4_t(bb, ws + brow*136 + bcol);
                mma16816(acc[2*fp],   a, &bb[0]);
                mma16816(acc[2*fp+1], a, &bb[2]);
            }
        }
        __syncthreads();
    }

    const float scale = (mat == 0) ? 0.08838834764831845f : 1.0f;
    const int row0 = r0 + wrp*16 + g;
    const int row1 = row0 + 8;
    #pragma unroll
    for (int f = 0; f < 16; f++) {
        const int col = f*8 + tg*2;
        *reinterpret_cast<uint32_t*>(op + (size_t)row0*H_ + col) =
            pack_h2(acc[f][0]*scale, acc[f][1]*scale);
        *reinterpret_cast<uint32_t*>(op + (size_t)row1*H_ + col) =
            pack_h2(acc[f][2]*scale, acc[f][3]*scale);
    }
}

// ---------------------------------------------------------------------------
// Flash attention: 64 q-rows, 4 warps, KV tiles of 64, 2-stage cp.async,
// fp16 single-term. smem 87 KB -> 2 CTAs/SM.
// ---------------------------------------------------------------------------
#define AT_ (64*136)

__global__ __launch_bounds__(128, 2) void attn_mma(float* __restrict__ out)
{
    extern __shared__ __half sma[];
    __half* Qs = sma;              // [64*136]
    __half* Ks = Qs + AT_;         // [2][64*136]
    __half* Vs = Ks + 2*AT_;       // [2][64*136]

    const int b    = blockIdx.y;
    const int qi   = (int)gridDim.x - 1 - (int)blockIdx.x;  // longest first
    const int q0   = qi * 64;
    const int tid  = threadIdx.x;
    const int wrp  = tid >> 5;
    const int lane = tid & 31;
    const int g    = lane >> 2;
    const int tg   = lane & 3;

    auto issue_kv = [&](int j, int s) {
        const __half* kp = gk + (size_t)(b*T_ + j*64) * H_;
        const __half* vp = gv + (size_t)(b*T_ + j*64) * H_;
        #pragma unroll
        for (int it = 0; it < 8; it++) {
            int idx = it*128 + tid;
            int row = idx >> 4, u = idx & 15;
            int d = row*136 + u*8;
            size_t src = (size_t)row*H_ + u*8;
            cp16(Ks + s*AT_ + d, kp + src);
            cp16(Vs + s*AT_ + d, vp + src);
        }
        cp_commit();
    };

    // prologue: Q + KV stage 0
    {
        const __half* qp = gq + (size_t)(b*T_ + q0) * H_;
        const __half* kp = gk + (size_t)(b*T_) * H_;
        const __half* vp = gv + (size_t)(b*T_) * H_;
        #pragma unroll
        for (int it = 0; it < 8; it++) {
            int idx = it*128 + tid;
            int row = idx >> 4, u = idx & 15;
            int d = row*136 + u*8;
            size_t src = (size_t)row*H_ + u*8;
            cp16(Qs + d, qp + src);
            cp16(Ks + d, kp + src);
            cp16(Vs + d, vp + src);
        }
        cp_commit();
    }

    float o[16][4];
    #pragma unroll
    for (int f = 0; f < 16; f++)
        #pragma unroll
        for (int e = 0; e < 4; e++) o[f][e] = 0.f;
    float m0 = -1e30f, m1 = -1e30f, l0 = 0.f, l1 = 0.f;

    for (int j = 0; j <= qi; j++) {
        const int s = j & 1;
        if (j < qi) { issue_kv(j+1, s^1); cp_wait<1>(); }
        else        { cp_wait<0>(); }
        __syncthreads();

        const __half* ks = Ks + s*AT_;
        const __half* vs = Vs + s*AT_;

        // ---- S = Q @ K^T  (64 x 64 x 128) ----
        float sv[8][4];
        #pragma unroll
        for (int f = 0; f < 8; f++)
            #pragma unroll
            for (int e = 0; e < 4; e++) sv[f][e] = 0.f;

        #pragma unroll
        for (int kk = 0; kk < 8; kk++) {
            uint32_t a[4];
            const int arow = 16*wrp + (lane & 15);
            const int acol = kk*16 + (lane >> 4) * 8;
            ldm_x4(a, Qs + arow*136 + acol);
            #pragma unroll
            for (int fp = 0; fp < 4; fp++) {
                uint32_t bb[4];
                const int brow = fp*16 + (lane & 7) + ((lane >> 4) & 1) * 8;
                const int bcol = kk*16 + ((lane >> 3) & 1) * 8;
                ldm_x4(bb, ks + brow*136 + bcol);
                mma16816(sv[2*fp],   a, &bb[0]);
                mma16816(sv[2*fp+1], a, &bb[2]);
            }
        }

        // ---- causal mask on diagonal tile ----
        if (j == qi) {
            #pragma unroll
            for (int f = 0; f < 8; f++) {
                #pragma unroll
                for (int e = 0; e < 4; e++) {
                    int col = f*8 + tg*2 + (e & 1);
                    int row = wrp*16 + g + ((e >> 1) ? 8 : 0);
                    if (col > row) sv[f][e] = -1e30f;
                }
            }
        }

        // ---- online softmax ----
        float rm0 = -1e30f, rm1 = -1e30f;
        #pragma unroll
        for (int f = 0; f < 8; f++) {
            rm0 = fmaxf(rm0, fmaxf(sv[f][0], sv[f][1]));
            rm1 = fmaxf(rm1, fmaxf(sv[f][2], sv[f][3]));
        }
        rm0 = fmaxf(rm0, __shfl_xor_sync(0xffffffffu, rm0, 1));
        rm0 = fmaxf(rm0, __shfl_xor_sync(0xffffffffu, rm0, 2));
        rm1 = fmaxf(rm1, __shfl_xor_sync(0xffffffffu, rm1, 1));
        rm1 = fmaxf(rm1, __shfl_xor_sync(0xffffffffu, rm1, 2));
        const float mn0 = fmaxf(m0, rm0), mn1 = fmaxf(m1, rm1);
        const float c0 = __expf(m0 - mn0), c1 = __expf(m1 - mn1);
        float ls0 = 0.f, ls1 = 0.f;
        #pragma unroll
        for (int f = 0; f < 8; f++) {
            sv[f][0] = __expf(sv[f][0] - mn0);
            sv[f][1] = __expf(sv[f][1] - mn0);
            sv[f][2] = __expf(sv[f][2] - mn1);
            sv[f][3] = __expf(sv[f][3] - mn1);
            ls0 += sv[f][0] + sv[f][1];
            ls1 += sv[f][2] + sv[f][3];
        }
        ls0 += __shfl_xor_sync(0xffffffffu, ls0, 1);
        ls0 += __shfl_xor_sync(0xffffffffu, ls0, 2);
        ls1 += __shfl_xor_sync(0xffffffffu, ls1, 1);
        ls1 += __shfl_xor_sync(0xffffffffu, ls1, 2);
        l0 = l0*c0 + ls0; l1 = l1*c1 + ls1;
        m0 = mn0; m1 = mn1;

        const bool noscale = (c0 == 1.0f) & (c1 == 1.0f);
        if (!__all_sync(0xffffffffu, noscale)) {
            #pragma unroll
            for (int f = 0; f < 16; f++) {
                o[f][0] *= c0; o[f][1] *= c0;
                o[f][2] *= c1; o[f][3] *= c1;
            }
        }

        // ---- O += P @ V  (64 x 128 x 64) ----
        #pragma unroll
        for (int kk = 0; kk < 4; kk++) {
            uint32_t a[4];
            a[0] = pack_h2(sv[2*kk][0],   sv[2*kk][1]);
            a[1] = pack_h2(sv[2*kk][2],   sv[2*kk][3]);
            a[2] = pack_h2(sv[2*kk+1][0], sv[2*kk+1][1]);
            a[3] = pack_h2(sv[2*kk+1][2], sv[2*kk+1][3]);
            const int brow = kk*16 + (lane & 7) + ((lane >> 3) & 1) * 8;
            #pragma unroll
            for (int fp = 0; fp < 8; fp++) {
                uint32_t bb[4];
                const int bcol = fp*16 + ((lane >> 4) & 1) * 8;
                ldm_x4_t(bb, vs + brow*136 + bcol);
                mma16816(o[2*fp],   a, &bb[0]);
                mma16816(o[2*fp+1], a, &bb[2]);
            }
        }
        __syncthreads();
    }

    // ---- epilogue ----
    const float inv0 = 1.0f / l0, inv1 = 1.0f / l1;
    const size_t row0 = (size_t)b*T_ + q0 + wrp*16 + g;
    const size_t row1 = row0 + 8;
    #pragma unroll
    for (int f = 0; f < 16; f++) {
        const int col = f*8 + tg*2;
        float2 v0 = make_float2(o[f][0]*inv0, o[f][1]*inv0);
        float2 v1 = make_float2(o[f][2]*inv1, o[f][3]*inv1);
        *reinterpret_cast<float2*>(out + row0*H_ + col) = v0;
        *reinterpret_cast<float2*>(out + row1*H_ + col) = v1;
    }
}

extern "C" void kernel_launch(void* const* d_in, const int* in_sizes, int n_in,
                              void* d_out, int out_size)
{
    const float* x  = (const float*)d_in[0];
    const float* Wq = (const float*)d_in[1];
    const float* Wk = (const float*)d_in[2];
    const float* Wv = (const float*)d_in[3];
    float* out = (float*)d_out;

    const int proj_smem = (2*PX_ + 2*PW_) * (int)sizeof(__half);   // 53248
    const int attn_smem = 5*AT_ * (int)sizeof(__half);             // 87040
    cudaFuncSetAttribute(proj_mma, cudaFuncAttributeMaxDynamicSharedMemorySize, proj_smem);
    cudaFuncSetAttribute(attn_mma, cudaFuncAttributeMaxDynamicSharedMemorySize, attn_smem);

    conv_x_kernel<<<BT_*E_/4/256, 256>>>(x);
    conv_w_kernel<<<dim3(E_*H_/4/256, 3), 256>>>(Wq, Wk, Wv);
    proj_mma<<<dim3(BT_/64, 3), 128, proj_smem>>>();
    attn_mma<<<dim3(T_/64, B_), 128, attn_smem>>>(out);
}

// round 10
// speedup vs baseline: 2.4302x; 1.0530x over previous
#include <cuda_runtime.h>
#include <cuda_fp16.h>
#include <stdint.h>

#define B_  8
#define T_  2048
#define E_  1024
#define H_  128
#define BT_ (B_*T_)

// ---- global scratch ----
__device__ __half gx[BT_*E_];
__device__ __half gw[3][E_*H_];
__device__ __half gq[BT_*H_];
__device__ __half gk[BT_*H_];
__device__ __half gv[BT_*H_];
__device__ float  go[2][BT_*H_];   // unnormalized partial O
__device__ float  gm[2][BT_];      // partial row max
__device__ float  gl[2][BT_];      // partial row sum

// ---- helpers ----
__device__ __forceinline__ void ldm_x4(uint32_t* r, const void* p) {
    uint32_t a = (uint32_t)__cvta_generic_to_shared(p);
    asm volatile("ldmatrix.sync.aligned.m8n8.x4.shared.b16 {%0,%1,%2,%3}, [%4];"
                 : "=r"(r[0]), "=r"(r[1]), "=r"(r[2]), "=r"(r[3]) : "r"(a));
}
__device__ __forceinline__ void ldm_x4_t(uint32_t* r, const void* p) {
    uint32_t a = (uint32_t)__cvta_generic_to_shared(p);
    asm volatile("ldmatrix.sync.aligned.m8n8.x4.trans.shared.b16 {%0,%1,%2,%3}, [%4];"
                 : "=r"(r[0]), "=r"(r[1]), "=r"(r[2]), "=r"(r[3]) : "r"(a));
}
__device__ __forceinline__ void mma16816(float* d, const uint32_t* a, const uint32_t* b) {
    asm volatile("mma.sync.aligned.m16n8k16.row.col.f32.f16.f16.f32 "
                 "{%0,%1,%2,%3}, {%4,%5,%6,%7}, {%8,%9}, {%0,%1,%2,%3};"
                 : "+f"(d[0]), "+f"(d[1]), "+f"(d[2]), "+f"(d[3])
                 : "r"(a[0]), "r"(a[1]), "r"(a[2]), "r"(a[3]), "r"(b[0]), "r"(b[1]));
}
__device__ __forceinline__ uint32_t pack_h2(float a, float b) {
    __half2 h;
    h.x = __float2half_rn(a);
    h.y = __float2half_rn(b);
    return *reinterpret_cast<uint32_t*>(&h);
}
__device__ __forceinline__ void cp16(void* smem, const void* gmem) {
    uint32_t a = (uint32_t)__cvta_generic_to_shared(smem);
    asm volatile("cp.async.cg.shared.global [%0], [%1], 16;" :: "r"(a), "l"(gmem));
}
__device__ __forceinline__ void cp_commit() { asm volatile("cp.async.commit_group;"); }
template<int N> __device__ __forceinline__ void cp_wait() {
    asm volatile("cp.async.wait_group %0;" :: "n"(N));
}

// ---------------------------------------------------------------------------
// Convert kernels
// ---------------------------------------------------------------------------
__global__ void conv_x_kernel(const float* __restrict__ x)
{
    int i = blockIdx.x * 256 + threadIdx.x;
    float4 v = reinterpret_cast<const float4*>(x)[i];
    uint2 hv;
    hv.x = pack_h2(v.x, v.y);
    hv.y = pack_h2(v.z, v.w);
    reinterpret_cast<uint2*>(gx)[i] = hv;
}

__global__ void conv_w_kernel(const float* __restrict__ Wq,
                              const float* __restrict__ Wk,
                              const float* __restrict__ Wv)
{
    const float* W = (blockIdx.y == 0) ? Wq : (blockIdx.y == 1) ? Wk : Wv;
    __half* o = gw[blockIdx.y];
    int i = blockIdx.x * 256 + threadIdx.x;
    float4 v = reinterpret_cast<const float4*>(W)[i];
    uint2 hv;
    hv.x = pack_h2(v.x, v.y);
    hv.y = pack_h2(v.z, v.w);
    reinterpret_cast<uint2*>(o)[i] = hv;
}

// ---------------------------------------------------------------------------
// Projection: 64x128 tile, BK=64, 4 warps, 2-stage cp.async, fp16.
// ---------------------------------------------------------------------------
#define PX_ (64*72)
#define PW_ (64*136)

__global__ __launch_bounds__(128, 2) void proj_mma()
{
    extern __shared__ __half smp[];
    __half* Xs = smp;               // [2][64*72]
    __half* Ws = Xs + 2*PX_;        // [2][64*136]

    const int mat = blockIdx.y;
    const __half* wp = gw[mat];
    __half* op = (mat == 0) ? gq : (mat == 1) ? gk : gv;

    const int r0   = blockIdx.x * 64;
    const int tid  = threadIdx.x;
    const int wrp  = tid >> 5;
    const int lane = tid & 31;
    const int g    = lane >> 2;
    const int tg   = lane & 3;

    auto issue = [&](int kc, int s) {
        const int k0 = kc * 64;
        #pragma unroll
        for (int it = 0; it < 4; it++) {
            int idx = it*128 + tid;
            int row = idx >> 3, u = idx & 7;
            cp16(Xs + s*PX_ + row*72 + u*8, gx + (size_t)(r0 + row) * E_ + k0 + u*8);
        }
        #pragma unroll
        for (int it = 0; it < 8; it++) {
            int idx = it*128 + tid;
            int row = idx >> 4, u = idx & 15;
            cp16(Ws + s*PW_ + row*136 + u*8, wp + (size_t)(k0 + row) * H_ + u*8);
        }
        cp_commit();
    };

    float acc[16][4];
    #pragma unroll
    for (int f = 0; f < 16; f++)
        #pragma unroll
        for (int e = 0; e < 4; e++) acc[f][e] = 0.f;

    issue(0, 0);

    for (int kc = 0; kc < 16; kc++) {
        const int s = kc & 1;
        if (kc < 15) { issue(kc+1, s^1); cp_wait<1>(); }
        else         { cp_wait<0>(); }
        __syncthreads();

        const __half* xs = Xs + s*PX_;
        const __half* ws = Ws + s*PW_;

        #pragma unroll
        for (int kk = 0; kk < 4; kk++) {
            uint32_t a[4];
            const int arow = 16*wrp + (lane & 15);
            const int acol = kk*16 + (lane >> 4) * 8;
            ldm_x4(a, xs + arow*72 + acol);
            const int brow = kk*16 + (lane & 7) + ((lane >> 3) & 1) * 8;
            #pragma unroll
            for (int fp = 0; fp < 8; fp++) {
                uint32_t bb[4];
                const int bcol = fp*16 + ((lane >> 4) & 1) * 8;
                ldm_x4_t(bb, ws + brow*136 + bcol);
                mma16816(acc[2*fp],   a, &bb[0]);
                mma16816(acc[2*fp+1], a, &bb[2]);
            }
        }
        __syncthreads();
    }

    const float scale = (mat == 0) ? 0.08838834764831845f : 1.0f;
    const int row0 = r0 + wrp*16 + g;
    const int row1 = row0 + 8;
    #pragma unroll
    for (int f = 0; f < 16; f++) {
        const int col = f*8 + tg*2;
        *reinterpret_cast<uint32_t*>(op + (size_t)row0*H_ + col) =
            pack_h2(acc[f][0]*scale, acc[f][1]*scale);
        *reinterpret_cast<uint32_t*>(op + (size_t)row1*H_ + col) =
            pack_h2(acc[f][2]*scale, acc[f][3]*scale);
    }
}

// ---------------------------------------------------------------------------
// Flash attention, split-KV(2): grid (2*T/64, B). Block pair (qi, part).
// Each part computes unnormalized O + (m, l) over its KV half.
// ---------------------------------------------------------------------------
#define AT_ (64*136)

__global__ __launch_bounds__(128, 2) void attn_mma()
{
    extern __shared__ __half sma[];
    __half* Qs = sma;              // [64*136]
    __half* Ks = Qs + AT_;         // [2][64*136]
    __half* Vs = Ks + 2*AT_;       // [2][64*136]

    const int b    = blockIdx.y;
    const int nq   = (int)gridDim.x >> 1;
    const int qi   = nq - 1 - ((int)blockIdx.x >> 1);   // longest first
    const int p    = blockIdx.x & 1;
    const int q0   = qi * 64;
    const int ntile = qi + 1;
    const int nh   = (ntile + 1) >> 1;                  // part0 tile count
    const int j0   = p ? nh : 0;
    const int j1   = p ? ntile : nh;
    const int tid  = threadIdx.x;
    const int wrp  = tid >> 5;
    const int lane = tid & 31;
    const int g    = lane >> 2;
    const int tg   = lane & 3;

    float o[16][4];
    #pragma unroll
    for (int f = 0; f < 16; f++)
        #pragma unroll
        for (int e = 0; e < 4; e++) o[f][e] = 0.f;
    float m0 = -1e30f, m1 = -1e30f, l0 = 0.f, l1 = 0.f;

    auto issue_kv = [&](int j, int s) {
        const __half* kp = gk + (size_t)(b*T_ + j*64) * H_;
        const __half* vp = gv + (size_t)(b*T_ + j*64) * H_;
        #pragma unroll
        for (int it = 0; it < 8; it++) {
            int idx = it*128 + tid;
            int row = idx >> 4, u = idx & 15;
            int d = row*136 + u*8;
            size_t src = (size_t)row*H_ + u*8;
            cp16(Ks + s*AT_ + d, kp + src);
            cp16(Vs + s*AT_ + d, vp + src);
        }
        cp_commit();
    };

    if (j1 > j0) {
        // prologue: Q + KV stage j0
        {
            const __half* qp = gq + (size_t)(b*T_ + q0) * H_;
            #pragma unroll
            for (int it = 0; it < 8; it++) {
                int idx = it*128 + tid;
                int row = idx >> 4, u = idx & 15;
                cp16(Qs + row*136 + u*8, qp + (size_t)row*H_ + u*8);
            }
            const __half* kp = gk + (size_t)(b*T_ + j0*64) * H_;
            const __half* vp = gv + (size_t)(b*T_ + j0*64) * H_;
            #pragma unroll
            for (int it = 0; it < 8; it++) {
                int idx = it*128 + tid;
                int row = idx >> 4, u = idx & 15;
                int d = row*136 + u*8;
                size_t src = (size_t)row*H_ + u*8;
                cp16(Ks + d, kp + src);
                cp16(Vs + d, vp + src);
            }
            cp_commit();
        }

        for (int j = j0; j < j1; j++) {
            const int s = (j - j0) & 1;
            if (j + 1 < j1) { issue_kv(j+1, s^1); cp_wait<1>(); }
            else            { cp_wait<0>(); }
            __syncthreads();

            const __half* ks = Ks + s*AT_;
            const __half* vs = Vs + s*AT_;

            // ---- S = Q @ K^T ----
            float sv[8][4];
            #pragma unroll
            for (int f = 0; f < 8; f++)
                #pragma unroll
                for (int e = 0; e < 4; e++) sv[f][e] = 0.f;

            #pragma unroll
            for (int kk = 0; kk < 8; kk++) {
                uint32_t a[4];
                const int arow = 16*wrp + (lane & 15);
                const int acol = kk*16 + (lane >> 4) * 8;
                ldm_x4(a, Qs + arow*136 + acol);
                #pragma unroll
                for (int fp = 0; fp < 4; fp++) {
                    uint32_t bb[4];
                    const int brow = fp*16 + (lane & 7) + ((lane >> 4) & 1) * 8;
                    const int bcol = kk*16 + ((lane >> 3) & 1) * 8;
                    ldm_x4(bb, ks + brow*136 + bcol);
                    mma16816(sv[2*fp],   a, &bb[0]);
                    mma16816(sv[2*fp+1], a, &bb[2]);
                }
            }

            // ---- causal mask (diagonal tile) ----
            if (j == qi) {
                #pragma unroll
                for (int f = 0; f < 8; f++) {
                    #pragma unroll
                    for (int e = 0; e < 4; e++) {
                        int col = f*8 + tg*2 + (e & 1);
                        int row = wrp*16 + g + ((e >> 1) ? 8 : 0);
                        if (col > row) sv[f][e] = -1e30f;
                    }
                }
            }

            // ---- online softmax ----
            float rm0 = -1e30f, rm1 = -1e30f;
            #pragma unroll
            for (int f = 0; f < 8; f++) {
                rm0 = fmaxf(rm0, fmaxf(sv[f][0], sv[f][1]));
                rm1 = fmaxf(rm1, fmaxf(sv[f][2], sv[f][3]));
            }
            rm0 = fmaxf(rm0, __shfl_xor_sync(0xffffffffu, rm0, 1));
            rm0 = fmaxf(rm0, __shfl_xor_sync(0xffffffffu, rm0, 2));
            rm1 = fmaxf(rm1, __shfl_xor_sync(0xffffffffu, rm1, 1));
            rm1 = fmaxf(rm1, __shfl_xor_sync(0xffffffffu, rm1, 2));
            const float mn0 = fmaxf(m0, rm0), mn1 = fmaxf(m1, rm1);
            const float c0 = __expf(m0 - mn0), c1 = __expf(m1 - mn1);
            float ls0 = 0.f, ls1 = 0.f;
            #pragma unroll
            for (int f = 0; f < 8; f++) {
                sv[f][0] = __expf(sv[f][0] - mn0);
                sv[f][1] = __expf(sv[f][1] - mn0);
                sv[f][2] = __expf(sv[f][2] - mn1);
                sv[f][3] = __expf(sv[f][3] - mn1);
                ls0 += sv[f][0] + sv[f][1];
                ls1 += sv[f][2] + sv[f][3];
            }
            ls0 += __shfl_xor_sync(0xffffffffu, ls0, 1);
            ls0 += __shfl_xor_sync(0xffffffffu, ls0, 2);
            ls1 += __shfl_xor_sync(0xffffffffu, ls1, 1);
            ls1 += __shfl_xor_sync(0xffffffffu, ls1, 2);
            l0 = l0*c0 + ls0; l1 = l1*c1 + ls1;
            m0 = mn0; m1 = mn1;

            const bool noscale = (c0 == 1.0f) & (c1 == 1.0f);
            if (!__all_sync(0xffffffffu, noscale)) {
                #pragma unroll
                for (int f = 0; f < 16; f++) {
                    o[f][0] *= c0; o[f][1] *= c0;
                    o[f][2] *= c1; o[f][3] *= c1;
                }
            }

            // ---- O += P @ V ----
            #pragma unroll
            for (int kk = 0; kk < 4; kk++) {
                uint32_t a[4];
                a[0] = pack_h2(sv[2*kk][0],   sv[2*kk][1]);
                a[1] = pack_h2(sv[2*kk][2],   sv[2*kk][3]);
                a[2] = pack_h2(sv[2*kk+1][0], sv[2*kk+1][1]);
                a[3] = pack_h2(sv[2*kk+1][2], sv[2*kk+1][3]);
                const int brow = kk*16 + (lane & 7) + ((lane >> 3) & 1) * 8;
                #pragma unroll
                for (int fp = 0; fp < 8; fp++) {
                    uint32_t bb[4];
                    const int bcol = fp*16 + ((lane >> 4) & 1) * 8;
                    ldm_x4_t(bb, vs + brow*136 + bcol);
                    mma16816(o[2*fp],   a, &bb[0]);
                    mma16816(o[2*fp+1], a, &bb[2]);
                }
            }
            __syncthreads();
        }
    }

    // ---- epilogue: write unnormalized O + (m, l) ----
    const size_t row0 = (size_t)b*T_ + q0 + wrp*16 + g;
    const size_t row1 = row0 + 8;
    float* gop = go[p];
    #pragma unroll
    for (int f = 0; f < 16; f++) {
        const int col = f*8 + tg*2;
        *reinterpret_cast<float2*>(gop + row0*H_ + col) = make_float2(o[f][0], o[f][1]);
        *reinterpret_cast<float2*>(gop + row1*H_ + col) = make_float2(o[f][2], o[f][3]);
    }
    if (tg == 0) {
        gm[p][row0] = m0; gl[p][row0] = l0;
        gm[p][row1] = m1; gl[p][row1] = l1;
    }
}

// ---------------------------------------------------------------------------
// Merge: out = (O0*e^(m0-m) + O1*e^(m1-m)) / (l0*e^(m0-m) + l1*e^(m1-m))
// ---------------------------------------------------------------------------
__global__ void merge_kernel(float* __restrict__ out)
{
    int i = blockIdx.x * 256 + threadIdx.x;     // float4 index over BT_*H_
    int row = i >> 5;                            // H_/4 = 32 float4 per row
    float pm0 = gm[0][row], pm1 = gm[1][row];
    float pl0 = gl[0][row], pl1 = gl[1][row];
    float m = fmaxf(pm0, pm1);
    float e0 = __expf(pm0 - m), e1 = __expf(pm1 - m);
    float inv = 1.0f / (pl0*e0 + pl1*e1);
    float4 a = reinterpret_cast<const float4*>(go[0])[i];
    float4 bq = reinterpret_cast<const float4*>(go[1])[i];
    float4 r;
    r.x = (a.x*e0 + bq.x*e1) * inv;
    r.y = (a.y*e0 + bq.y*e1) * inv;
    r.z = (a.z*e0 + bq.z*e1) * inv;
    r.w = (a.w*e0 + bq.w*e1) * inv;
    reinterpret_cast<float4*>(out)[i] = r;
}

extern "C" void kernel_launch(void* const* d_in, const int* in_sizes, int n_in,
                              void* d_out, int out_size)
{
    const float* x  = (const float*)d_in[0];
    const float* Wq = (const float*)d_in[1];
    const float* Wk = (const float*)d_in[2];
    const float* Wv = (const float*)d_in[3];
    float* out = (float*)d_out;

    const int proj_smem = (2*PX_ + 2*PW_) * (int)sizeof(__half);   // 53248
    const int attn_smem = 5*AT_ * (int)sizeof(__half);             // 87040
    cudaFuncSetAttribute(proj_mma, cudaFuncAttributeMaxDynamicSharedMemorySize, proj_smem);
    cudaFuncSetAttribute(attn_mma, cudaFuncAttributeMaxDynamicSharedMemorySize, attn_smem);

    conv_x_kernel<<<BT_*E_/4/256, 256>>>(x);
    conv_w_kernel<<<dim3(E_*H_/4/256, 3), 256>>>(Wq, Wk, Wv);
    proj_mma<<<dim3(BT_/64, 3), 128, proj_smem>>>();
    attn_mma<<<dim3(2*T_/64, B_), 128, attn_smem>>>();
    merge_kernel<<<BT_*H_/4/256, 256>>>(out);
}

// round 11
// speedup vs baseline: 2.6458x; 1.0887x over previous
#include <cuda_runtime.h>
#include <cuda_fp16.h>
#include <stdint.h>

#define B_  8
#define T_  2048
#define E_  1024
#define H_  128
#define BT_ (B_*T_)
#define NSPLIT 4

// ---- global scratch ----
__device__ __half gx[BT_*E_];
__device__ __half gw[3][E_*H_];
__device__ __half gq[BT_*H_];
__device__ __half gk[BT_*H_];
__device__ __half gv[BT_*H_];
__device__ float  go[NSPLIT][BT_*H_];   // unnormalized partial O
__device__ float  gm[NSPLIT][BT_];      // partial row max
__device__ float  gl[NSPLIT][BT_];      // partial row sum

// ---- helpers ----
__device__ __forceinline__ void ldm_x4(uint32_t* r, const void* p) {
    uint32_t a = (uint32_t)__cvta_generic_to_shared(p);
    asm volatile("ldmatrix.sync.aligned.m8n8.x4.shared.b16 {%0,%1,%2,%3}, [%4];"
                 : "=r"(r[0]), "=r"(r[1]), "=r"(r[2]), "=r"(r[3]) : "r"(a));
}
__device__ __forceinline__ void ldm_x4_t(uint32_t* r, const void* p) {
    uint32_t a = (uint32_t)__cvta_generic_to_shared(p);
    asm volatile("ldmatrix.sync.aligned.m8n8.x4.trans.shared.b16 {%0,%1,%2,%3}, [%4];"
                 : "=r"(r[0]), "=r"(r[1]), "=r"(r[2]), "=r"(r[3]) : "r"(a));
}
__device__ __forceinline__ void mma16816(float* d, const uint32_t* a, const uint32_t* b) {
    asm volatile("mma.sync.aligned.m16n8k16.row.col.f32.f16.f16.f32 "
                 "{%0,%1,%2,%3}, {%4,%5,%6,%7}, {%8,%9}, {%0,%1,%2,%3};"
                 : "+f"(d[0]), "+f"(d[1]), "+f"(d[2]), "+f"(d[3])
                 : "r"(a[0]), "r"(a[1]), "r"(a[2]), "r"(a[3]), "r"(b[0]), "r"(b[1]));
}
__device__ __forceinline__ uint32_t pack_h2(float a, float b) {
    __half2 h;
    h.x = __float2half_rn(a);
    h.y = __float2half_rn(b);
    return *reinterpret_cast<uint32_t*>(&h);
}
__device__ __forceinline__ void cp16(void* smem, const void* gmem) {
    uint32_t a = (uint32_t)__cvta_generic_to_shared(smem);
    asm volatile("cp.async.cg.shared.global [%0], [%1], 16;" :: "r"(a), "l"(gmem));
}
__device__ __forceinline__ void cp_commit() { asm volatile("cp.async.commit_group;"); }
template<int N> __device__ __forceinline__ void cp_wait() {
    asm volatile("cp.async.wait_group %0;" :: "n"(N));
}

// ---------------------------------------------------------------------------
// Convert kernels
// ---------------------------------------------------------------------------
__global__ void conv_x_kernel(const float* __restrict__ x)
{
    int i = blockIdx.x * 256 + threadIdx.x;
    float4 v = reinterpret_cast<const float4*>(x)[i];
    uint2 hv;
    hv.x = pack_h2(v.x, v.y);
    hv.y = pack_h2(v.z, v.w);
    reinterpret_cast<uint2*>(gx)[i] = hv;
}

__global__ void conv_w_kernel(const float* __restrict__ Wq,
                              const float* __restrict__ Wk,
                              const float* __restrict__ Wv)
{
    const float* W = (blockIdx.y == 0) ? Wq : (blockIdx.y == 1) ? Wk : Wv;
    __half* o = gw[blockIdx.y];
    int i = blockIdx.x * 256 + threadIdx.x;
    float4 v = reinterpret_cast<const float4*>(W)[i];
    uint2 hv;
    hv.x = pack_h2(v.x, v.y);
    hv.y = pack_h2(v.z, v.w);
    reinterpret_cast<uint2*>(o)[i] = hv;
}

// ---------------------------------------------------------------------------
// Projection: 128x128 CTA tile, 8 warps (warp tile 32x64), BK=64,
// 2-stage cp.async, fp16. smem 71.7 KB -> 2 CTAs/SM.
// ---------------------------------------------------------------------------
#define PX_ (128*72)
#define PW_ (64*136)

__global__ __launch_bounds__(256, 2) void proj_mma()
{
    extern __shared__ __half smp[];
    __half* Xs = smp;               // [2][128*72]
    __half* Ws = Xs + 2*PX_;        // [2][64*136]

    const int mat = blockIdx.y;
    const __half* wp = gw[mat];
    __half* op = (mat == 0) ? gq : (mat == 1) ? gk : gv;

    const int r0   = blockIdx.x * 128;
    const int tid  = threadIdx.x;
    const int wrp  = tid >> 5;
    const int lane = tid & 31;
    const int mw   = wrp & 3;
    const int nw   = wrp >> 2;
    const int g    = lane >> 2;
    const int tg   = lane & 3;

    auto issue = [&](int kc, int s) {
        const int k0 = kc * 64;
        #pragma unroll
        for (int it = 0; it < 4; it++) {
            int idx = it*256 + tid;
            int row = idx >> 3, u = idx & 7;
            cp16(Xs + s*PX_ + row*72 + u*8, gx + (size_t)(r0 + row) * E_ + k0 + u*8);
        }
        #pragma unroll
        for (int it = 0; it < 4; it++) {
            int idx = it*256 + tid;
            int row = idx >> 4, u = idx & 15;
            cp16(Ws + s*PW_ + row*136 + u*8, wp + (size_t)(k0 + row) * H_ + u*8);
        }
        cp_commit();
    };

    float acc[2][8][4];
    #pragma unroll
    for (int mf = 0; mf < 2; mf++)
        #pragma unroll
        for (int f = 0; f < 8; f++)
            #pragma unroll
            for (int e = 0; e < 4; e++) acc[mf][f][e] = 0.f;

    issue(0, 0);

    for (int kc = 0; kc < 16; kc++) {
        const int s = kc & 1;
        if (kc < 15) { issue(kc+1, s^1); cp_wait<1>(); }
        else         { cp_wait<0>(); }
        __syncthreads();

        const __half* xs = Xs + s*PX_;
        const __half* ws = Ws + s*PW_;

        #pragma unroll
        for (int kk = 0; kk < 4; kk++) {
            uint32_t a[2][4];
            #pragma unroll
            for (int mf = 0; mf < 2; mf++) {
                const int arow = mw*32 + mf*16 + (lane & 15);
                const int acol = kk*16 + (lane >> 4) * 8;
                ldm_x4(a[mf], xs + arow*72 + acol);
            }
            const int brow = kk*16 + (lane & 7) + ((lane >> 3) & 1) * 8;
            #pragma unroll
            for (int fp = 0; fp < 4; fp++) {
                uint32_t bb[4];
                const int bcol = nw*64 + fp*16 + ((lane >> 4) & 1) * 8;
                ldm_x4_t(bb, ws + brow*136 + bcol);
                #pragma unroll
                for (int mf = 0; mf < 2; mf++) {
                    mma16816(acc[mf][2*fp],   a[mf], &bb[0]);
                    mma16816(acc[mf][2*fp+1], a[mf], &bb[2]);
                }
            }
        }
        __syncthreads();
    }

    const float scale = (mat == 0) ? 0.08838834764831845f : 1.0f;
    #pragma unroll
    for (int mf = 0; mf < 2; mf++) {
        const int row0 = r0 + mw*32 + mf*16 + g;
        const int row1 = row0 + 8;
        #pragma unroll
        for (int f = 0; f < 8; f++) {
            const int col = nw*64 + f*8 + tg*2;
            *reinterpret_cast<uint32_t*>(op + (size_t)row0*H_ + col) =
                pack_h2(acc[mf][f][0]*scale, acc[mf][f][1]*scale);
            *reinterpret_cast<uint32_t*>(op + (size_t)row1*H_ + col) =
                pack_h2(acc[mf][f][2]*scale, acc[mf][f][3]*scale);
        }
    }
}

// ---------------------------------------------------------------------------
// Flash attention, split-KV(4): grid (4*T/64, B). Block (qi, part).
// ---------------------------------------------------------------------------
#define AT_ (64*136)

__global__ __launch_bounds__(128, 2) void attn_mma()
{
    extern __shared__ __half sma[];
    __half* Qs = sma;              // [64*136]
    __half* Ks = Qs + AT_;         // [2][64*136]
    __half* Vs = Ks + 2*AT_;       // [2][64*136]

    const int b    = blockIdx.y;
    const int nq   = (int)gridDim.x / NSPLIT;
    const int qi   = nq - 1 - ((int)blockIdx.x / NSPLIT);   // longest first
    const int p    = blockIdx.x % NSPLIT;
    const int q0   = qi * 64;
    const int ntile = qi + 1;
    const int j0   = (ntile * p) / NSPLIT;
    const int j1   = (ntile * (p + 1)) / NSPLIT;
    const int tid  = threadIdx.x;
    const int wrp  = tid >> 5;
    const int lane = tid & 31;
    const int g    = lane >> 2;
    const int tg   = lane & 3;

    float o[16][4];
    #pragma unroll
    for (int f = 0; f < 16; f++)
        #pragma unroll
        for (int e = 0; e < 4; e++) o[f][e] = 0.f;
    float m0 = -1e30f, m1 = -1e30f, l0 = 0.f, l1 = 0.f;

    auto issue_kv = [&](int j, int s) {
        const __half* kp = gk + (size_t)(b*T_ + j*64) * H_;
        const __half* vp = gv + (size_t)(b*T_ + j*64) * H_;
        #pragma unroll
        for (int it = 0; it < 8; it++) {
            int idx = it*128 + tid;
            int row = idx >> 4, u = idx & 15;
            int d = row*136 + u*8;
            size_t src = (size_t)row*H_ + u*8;
            cp16(Ks + s*AT_ + d, kp + src);
            cp16(Vs + s*AT_ + d, vp + src);
        }
        cp_commit();
    };

    if (j1 > j0) {
        // prologue: Q + KV stage j0
        {
            const __half* qp = gq + (size_t)(b*T_ + q0) * H_;
            #pragma unroll
            for (int it = 0; it < 8; it++) {
                int idx = it*128 + tid;
                int row = idx >> 4, u = idx & 15;
                cp16(Qs + row*136 + u*8, qp + (size_t)row*H_ + u*8);
            }
            const __half* kp = gk + (size_t)(b*T_ + j0*64) * H_;
            const __half* vp = gv + (size_t)(b*T_ + j0*64) * H_;
            #pragma unroll
            for (int it = 0; it < 8; it++) {
                int idx = it*128 + tid;
                int row = idx >> 4, u = idx & 15;
                int d = row*136 + u*8;
                size_t src = (size_t)row*H_ + u*8;
                cp16(Ks + d, kp + src);
                cp16(Vs + d, vp + src);
            }
            cp_commit();
        }

        for (int j = j0; j < j1; j++) {
            const int s = (j - j0) & 1;
            if (j + 1 < j1) { issue_kv(j+1, s^1); cp_wait<1>(); }
            else            { cp_wait<0>(); }
            __syncthreads();

            const __half* ks = Ks + s*AT_;
            const __half* vs = Vs + s*AT_;

            // ---- S = Q @ K^T ----
            float sv[8][4];
            #pragma unroll
            for (int f = 0; f < 8; f++)
                #pragma unroll
                for (int e = 0; e < 4; e++) sv[f][e] = 0.f;

            #pragma unroll
            for (int kk = 0; kk < 8; kk++) {
                uint32_t a[4];
                const int arow = 16*wrp + (lane & 15);
                const int acol = kk*16 + (lane >> 4) * 8;
                ldm_x4(a, Qs + arow*136 + acol);
                #pragma unroll
                for (int fp = 0; fp < 4; fp++) {
                    uint32_t bb[4];
                    const int brow = fp*16 + (lane & 7) + ((lane >> 4) & 1) * 8;
                    const int bcol = kk*16 + ((lane >> 3) & 1) * 8;
                    ldm_x4(bb, ks + brow*136 + bcol);
                    mma16816(sv[2*fp],   a, &bb[0]);
                    mma16816(sv[2*fp+1], a, &bb[2]);
                }
            }

            // ---- causal mask (diagonal tile) ----
            if (j == qi) {
                #pragma unroll
                for (int f = 0; f < 8; f++) {
                    #pragma unroll
                    for (int e = 0; e < 4; e++) {
                        int col = f*8 + tg*2 + (e & 1);
                        int row = wrp*16 + g + ((e >> 1) ? 8 : 0);
                        if (col > row) sv[f][e] = -1e30f;
                    }
                }
            }

            // ---- online softmax ----
            float rm0 = -1e30f, rm1 = -1e30f;
            #pragma unroll
            for (int f = 0; f < 8; f++) {
                rm0 = fmaxf(rm0, fmaxf(sv[f][0], sv[f][1]));
                rm1 = fmaxf(rm1, fmaxf(sv[f][2], sv[f][3]));
            }
            rm0 = fmaxf(rm0, __shfl_xor_sync(0xffffffffu, rm0, 1));
            rm0 = fmaxf(rm0, __shfl_xor_sync(0xffffffffu, rm0, 2));
            rm1 = fmaxf(rm1, __shfl_xor_sync(0xffffffffu, rm1, 1));
            rm1 = fmaxf(rm1, __shfl_xor_sync(0xffffffffu, rm1, 2));
            const float mn0 = fmaxf(m0, rm0), mn1 = fmaxf(m1, rm1);
            const float c0 = __expf(m0 - mn0), c1 = __expf(m1 - mn1);
            float ls0 = 0.f, ls1 = 0.f;
            #pragma unroll
            for (int f = 0; f < 8; f++) {
                sv[f][0] = __expf(sv[f][0] - mn0);
                sv[f][1] = __expf(sv[f][1] - mn0);
                sv[f][2] = __expf(sv[f][2] - mn1);
                sv[f][3] = __expf(sv[f][3] - mn1);
                ls0 += sv[f][0] + sv[f][1];
                ls1 += sv[f][2] + sv[f][3];
            }
            ls0 += __shfl_xor_sync(0xffffffffu, ls0, 1);
            ls0 += __shfl_xor_sync(0xffffffffu, ls0, 2);
            ls1 += __shfl_xor_sync(0xffffffffu, ls1, 1);
            ls1 += __shfl_xor_sync(0xffffffffu, ls1, 2);
            l0 = l0*c0 + ls0; l1 = l1*c1 + ls1;
            m0 = mn0; m1 = mn1;

            const bool noscale = (c0 == 1.0f) & (c1 == 1.0f);
            if (!__all_sync(0xffffffffu, noscale)) {
                #pragma unroll
                for (int f = 0; f < 16; f++) {
                    o[f][0] *= c0; o[f][1] *= c0;
                    o[f][2] *= c1; o[f][3] *= c1;
                }
            }

            // ---- O += P @ V ----
            #pragma unroll
            for (int kk = 0; kk < 4; kk++) {
                uint32_t a[4];
                a[0] = pack_h2(sv[2*kk][0],   sv[2*kk][1]);
                a[1] = pack_h2(sv[2*kk][2],   sv[2*kk][3]);
                a[2] = pack_h2(sv[2*kk+1][0], sv[2*kk+1][1]);
                a[3] = pack_h2(sv[2*kk+1][2], sv[2*kk+1][3]);
                const int brow = kk*16 + (lane & 7) + ((lane >> 3) & 1) * 8;
                #pragma unroll
                for (int fp = 0; fp < 8; fp++) {
                    uint32_t bb[4];
                    const int bcol = fp*16 + ((lane >> 4) & 1) * 8;
                    ldm_x4_t(bb, vs + brow*136 + bcol);
                    mma16816(o[2*fp],   a, &bb[0]);
                    mma16816(o[2*fp+1], a, &bb[2]);
                }
            }
            __syncthreads();
        }
    }

    // ---- epilogue: write unnormalized O + (m, l) ----
    const size_t row0 = (size_t)b*T_ + q0 + wrp*16 + g;
    const size_t row1 = row0 + 8;
    float* gop = go[p];
    #pragma unroll
    for (int f = 0; f < 16; f++) {
        const int col = f*8 + tg*2;
        *reinterpret_cast<float2*>(gop + row0*H_ + col) = make_float2(o[f][0], o[f][1]);
        *reinterpret_cast<float2*>(gop + row1*H_ + col) = make_float2(o[f][2], o[f][3]);
    }
    if (tg == 0) {
        gm[p][row0] = m0; gl[p][row0] = l0;
        gm[p][row1] = m1; gl[p][row1] = l1;
    }
}

// ---------------------------------------------------------------------------
// Merge 4 partials.
// ---------------------------------------------------------------------------
__global__ void merge_kernel(float* __restrict__ out)
{
    int i = blockIdx.x * 256 + threadIdx.x;     // float4 index over BT_*H_
    int row = i >> 5;
    float pm[NSPLIT], pl[NSPLIT];
    float m = -1e30f;
    #pragma unroll
    for (int p = 0; p < NSPLIT; p++) {
        pm[p] = gm[p][row];
        pl[p] = gl[p][row];
        m = fmaxf(m, pm[p]);
    }
    float e[NSPLIT], lsum = 0.f;
    #pragma unroll
    for (int p = 0; p < NSPLIT; p++) {
        e[p] = __expf(pm[p] - m);
        lsum += pl[p] * e[p];
    }
    float inv = 1.0f / lsum;
    float4 r = make_float4(0.f, 0.f, 0.f, 0.f);
    #pragma unroll
    for (int p = 0; p < NSPLIT; p++) {
        float4 a = reinterpret_cast<const float4*>(go[p])[i];
        r.x += a.x * e[p];
        r.y += a.y * e[p];
        r.z += a.z * e[p];
        r.w += a.w * e[p];
    }
    r.x *= inv; r.y *= inv; r.z *= inv; r.w *= inv;
    reinterpret_cast<float4*>(out)[i] = r;
}

extern "C" void kernel_launch(void* const* d_in, const int* in_sizes, int n_in,
                              void* d_out, int out_size)
{
    const float* x  = (const float*)d_in[0];
    const float* Wq = (const float*)d_in[1];
    const float* Wk = (const float*)d_in[2];
    const float* Wv = (const float*)d_in[3];
    float* out = (float*)d_out;

    const int proj_smem = (2*PX_ + 2*PW_) * (int)sizeof(__half);   // 71680
    const int attn_smem = 5*AT_ * (int)sizeof(__half);             // 87040
    cudaFuncSetAttribute(proj_mma, cudaFuncAttributeMaxDynamicSharedMemorySize, proj_smem);
    cudaFuncSetAttribute(attn_mma, cudaFuncAttributeMaxDynamicSharedMemorySize, attn_smem);

    conv_x_kernel<<<BT_*E_/4/256, 256>>>(x);
    conv_w_kernel<<<dim3(E_*H_/4/256, 3), 256>>>(Wq, Wk, Wv);
    proj_mma<<<dim3(BT_/128, 3), 256, proj_smem>>>();
    attn_mma<<<dim3(NSPLIT*T_/64, B_), 128, attn_smem>>>();
    merge_kernel<<<BT_*H_/4/256, 256>>>(out);
}